// round 9
// baseline (speedup 1.0000x reference)
#include <cuda_runtime.h>
#include <math.h>

#define BSZ 4
#define SEQ 2048
#define DIMX 2048
#define NH 16
#define HD 128
#define TOK (BSZ*SEQ)   // 8192

// ---------------- scratch (device globals; no cudaMalloc allowed) ----------
__device__ float g_q[BSZ*NH*SEQ*HD];   // [bh][s][d]  fp32 then tf32 after norm
__device__ float g_k[BSZ*NH*SEQ*HD];
__device__ float g_v[BSZ*NH*SEQ*HD];   // fp32
__device__ float g_vt[BSZ*NH*HD*SEQ];  // [bh][d][s]  tf32 bits
__device__ float g_y[TOK*DIMX];        // attention out, [token][dim] fp32

// ---------------- helpers ---------------------------------------------------
__device__ __forceinline__ unsigned f2tf(float x) {
    unsigned u;
    asm("cvt.rna.tf32.f32 %0, %1;" : "=r"(u) : "f"(x));
    return u;
}
__device__ __forceinline__ unsigned u2tf(unsigned x) {
    unsigned u;
    asm("cvt.rna.tf32.f32 %0, %1;" : "=r"(u) : "f"(__uint_as_float(x)));
    return u;
}
__device__ __forceinline__ void ldsm4(unsigned r[4], unsigned addr) {
    asm volatile("ldmatrix.sync.aligned.m8n8.x4.shared.b16 {%0,%1,%2,%3}, [%4];"
                 : "=r"(r[0]), "=r"(r[1]), "=r"(r[2]), "=r"(r[3]) : "r"(addr));
}
__device__ __forceinline__ void mma8(float d[4], const unsigned a[4], const unsigned b[2]) {
    asm volatile("mma.sync.aligned.m16n8k8.row.col.f32.tf32.tf32.f32 "
                 "{%0,%1,%2,%3}, {%4,%5,%6,%7}, {%8,%9}, {%0,%1,%2,%3};"
                 : "+f"(d[0]), "+f"(d[1]), "+f"(d[2]), "+f"(d[3])
                 : "r"(a[0]), "r"(a[1]), "r"(a[2]), "r"(a[3]), "r"(b[0]), "r"(b[1]));
}
__device__ __forceinline__ void cpa16(unsigned s, const void* g) {
    asm volatile("cp.async.cg.shared.global [%0], [%1], 16;" :: "r"(s), "l"(g));
}
__device__ __forceinline__ void cp_commit() {
    asm volatile("cp.async.commit_group;");
}
template<int N> __device__ __forceinline__ void cp_wait() {
    asm volatile("cp.async.wait_group %0;" :: "n"(N));
}

// ---------------- tf32 GEMM: C[m][n] = sum_k A[m][k]*B[n][k] ----------------
// block 128x128, BK=32, 3-stage cp.async pipeline, 8 warps 2(m)x4(n),
// warp tile 64x32 of m16n8k8. cvt->tf32 applied on fragments post-ldsm.
// mode 0: plain store. mode 1: qkv scatter. A==nullptr -> use g_y.
#define GS (128*36)
#define GEMM_SMEM_BYTES (3 * 2 * GS * 4)

__global__ __launch_bounds__(256)
void gemm_tf32_kernel(const float* __restrict__ A, const float* __restrict__ B,
                      float* __restrict__ C, int M, int N, int K, int mode)
{
    extern __shared__ __align__(16) float gsm[];
    if (A == nullptr) A = g_y;

    const int tid = threadIdx.x;
    const int l = tid & 31, w = tid >> 5;
    const int wm = w >> 2, wn = w & 3;
    const int m0 = blockIdx.y * 128, n0 = blockIdx.x * 128;

    const int lr = tid >> 3;            // 0..31 (+32*i)
    const int lc = (tid & 7) << 2;      // 0..28

    const float* Ap = A + (size_t)m0 * K;
    const float* Bp = B + (size_t)n0 * K;

    const unsigned smA = (unsigned)__cvta_generic_to_shared(gsm);
    const unsigned smB = smA + 3 * GS * 4;
    const unsigned ldA = smA + ((lr * 36 + lc) << 2);
    const unsigned ldB = smB + ((lr * 36 + lc) << 2);

    const int ntile = K / 32;

    // issue stage kt (one commit group covers A+B)
    auto issue = [&](int kt) {
        if (kt < ntile) {
            const int st = kt % 3;
            const int ko = kt * 32 + lc;
            const unsigned da = ldA + st * (GS * 4);
            const unsigned db = ldB + st * (GS * 4);
#pragma unroll
            for (int i = 0; i < 4; i++) {
                cpa16(da + i * (32 * 36 * 4), Ap + (size_t)(lr + 32 * i) * K + ko);
                cpa16(db + i * (32 * 36 * 4), Bp + (size_t)(lr + 32 * i) * K + ko);
            }
        }
        cp_commit();
    };

    float acc[4][4][4];
#pragma unroll
    for (int a = 0; a < 4; a++)
#pragma unroll
        for (int b = 0; b < 4; b++)
#pragma unroll
            for (int v = 0; v < 4; v++) acc[a][b][v] = 0.f;

    const unsigned aAddr = smA + (((wm*64 + ((l>>3)&1)*8 + (l&7))*36 + ((l>>4)<<2)) << 2);
    const unsigned bAddr = smB + (((wn*32 + ((l>>4)<<3) + (l&7))*36 + (((l>>3)&1)<<2)) << 2);

    issue(0);
    issue(1);

    for (int kt = 0; kt < ntile; kt++) {
        cp_wait<1>();          // stage kt complete (self)
        __syncthreads();       // publish stage kt; all warps done stage kt-1
        issue(kt + 2);         // overwrites buf (kt-1)%3 — safe after barrier

        const unsigned soff = (kt % 3) * (GS * 4);
#pragma unroll
        for (int ks = 0; ks < 4; ks++) {
            unsigned af[4][4], bf[2][4];
#pragma unroll
            for (int mt = 0; mt < 4; mt++) {
                ldsm4(af[mt], aAddr + soff + ((mt*16*36 + ks*8) << 2));
#pragma unroll
                for (int r = 0; r < 4; r++) af[mt][r] = u2tf(af[mt][r]);
            }
#pragma unroll
            for (int nb = 0; nb < 2; nb++) {
                ldsm4(bf[nb], bAddr + soff + ((nb*16*36 + ks*8) << 2));
#pragma unroll
                for (int r = 0; r < 4; r++) bf[nb][r] = u2tf(bf[nb][r]);
            }
#pragma unroll
            for (int mt = 0; mt < 4; mt++)
#pragma unroll
                for (int nt = 0; nt < 4; nt++)
                    mma8(acc[mt][nt], af[mt], &bf[nt>>1][(nt&1)*2]);
        }
    }

    const int g = l >> 2, c = l & 3;
    if (mode == 0) {
#pragma unroll
        for (int mt = 0; mt < 4; mt++)
#pragma unroll
            for (int nt = 0; nt < 4; nt++) {
                int m = m0 + wm*64 + mt*16 + g;
                int n = n0 + wn*32 + nt*8 + 2*c;
                *(float2*)&C[(size_t)m*N + n]     = make_float2(acc[mt][nt][0], acc[mt][nt][1]);
                *(float2*)&C[(size_t)(m+8)*N + n] = make_float2(acc[mt][nt][2], acc[mt][nt][3]);
            }
    } else {
        const int which = n0 >> 11;
        const int h = (n0 >> 7) & 15;
        float* dst = (which == 0) ? g_q : (which == 1) ? g_k : g_v;
#pragma unroll
        for (int mt = 0; mt < 4; mt++)
#pragma unroll
            for (int nt = 0; nt < 4; nt++) {
                int m = m0 + wm*64 + mt*16 + g;
                int b_ = m >> 11, s = m & 2047;
                int d = wn*32 + nt*8 + 2*c;
                float* p = dst + (((size_t)(b_*NH + h)*SEQ + s)*HD + d);
                *(float2*)p            = make_float2(acc[mt][nt][0], acc[mt][nt][1]);
                *(float2*)(p + 8*HD)   = make_float2(acc[mt][nt][2], acc[mt][nt][3]);
            }
    }
}

// ---------------- RMSNorm + RoPE on q,k (in place, output tf32 bits) -------
__global__ void norm_rope_kernel(const float* __restrict__ qw,
                                 const float* __restrict__ kw)
{
    const int NROW = BSZ * NH * SEQ;
    int gw = (blockIdx.x * blockDim.x + threadIdx.x) >> 5;
    int lane = threadIdx.x & 31;
    int tensor = (gw >= NROW);
    int row = tensor ? gw - NROW : gw;
    float* base = (tensor ? g_k : g_q) + (size_t)row * HD;
    const float* w = tensor ? kw : qw;
    const int s = row & (SEQ - 1);
    const float qscale = tensor ? 1.0f : 0.08838834764831845f;  // 128^-0.5 on q only

    float4 v = *(const float4*)(base + lane * 4);
    float ss = v.x*v.x + v.y*v.y + v.z*v.z + v.w*v.w;
#pragma unroll
    for (int off = 16; off; off >>= 1)
        ss += __shfl_xor_sync(0xffffffffu, ss, off);
    const float inv = rsqrtf(ss * (1.0f / HD) + 1e-6f);

    const float4 wv = *(const float4*)(w + lane * 4);
    float xv[4];
    xv[0] = v.x * inv * wv.x; xv[1] = v.y * inv * wv.y;
    xv[2] = v.z * inv * wv.z; xv[3] = v.w * inv * wv.w;

    unsigned ov[4];
#pragma unroll
    for (int u = 0; u < 4; u++) {
        float other = __shfl_xor_sync(0xffffffffu, xv[u], 16);
        int i = ((lane & 15) << 2) + u;               // freq index 0..63
        float freq = exp2f(-5.0f * (float)i * (1.0f / 64.0f));  // 32^(-i/64)
        float ang = (float)s * freq;
        float sn, cs;
        sincosf(ang, &sn, &cs);
        float r = (lane < 16) ? (xv[u]*cs - other*sn) : (xv[u]*cs + other*sn);
        ov[u] = f2tf(r * qscale);
    }
    *(uint4*)(base + lane * 4) = make_uint4(ov[0], ov[1], ov[2], ov[3]);
}

// ---------------- V transpose: g_v[bh][s][d] -> g_vt[bh][d][s] (tf32) ------
__global__ void transpose_v_kernel()
{
    __shared__ float t[32][33];
    const int bh = blockIdx.z;
    const int s0 = blockIdx.x * 32, d0 = blockIdx.y * 32;
    const int tx = threadIdx.x, ty = threadIdx.y;
    const float* src = g_v + (size_t)bh * SEQ * HD;
    float* dst = g_vt + (size_t)bh * HD * SEQ;
#pragma unroll
    for (int j = 0; j < 4; j++)
        t[ty + 8*j][tx] = src[(size_t)(s0 + ty + 8*j) * HD + d0 + tx];
    __syncthreads();
#pragma unroll
    for (int j = 0; j < 4; j++)
        dst[(size_t)(d0 + ty + 8*j) * SEQ + s0 + tx] =
            __uint_as_float(f2tf(t[tx][ty + 8*j]));
}

// ---------------- flash attention (tf32 mma, cp.async pipelined) -----------
// grid (SEQ/128, BSZ*NH), block 256 (8 warps). Warp w owns q rows 16w..16w+15.
// K tile double-buffered; V load overlapped with S compute.
// smem floats: Qs[128*132] | Ks[2][64*132] | Vt[128*68] | Ps[128*68]
#define OFF_KS  (128*132)
#define KS_ST   (64*132)
#define OFF_VT  (OFF_KS + 2*KS_ST)
#define OFF_PS  (OFF_VT + 128*68)
#define ATTN_SMEM_BYTES ((OFF_PS + 128*68) * 4)

__global__ __launch_bounds__(256)
void attn_kernel()
{
    extern __shared__ __align__(16) float sm[];
    float* Qs = sm;

    const int tid = threadIdx.x;
    const int w = tid >> 5, l = tid & 31;
    const int g = l >> 2, c = l & 3;
    const int bh = blockIdx.y, b = bh >> 4, h = bh & 15;
    const int q0 = blockIdx.x * 128;
    const float* Qg = g_q + ((size_t)bh * SEQ + q0) * HD;
    const float* Kg = g_k + (size_t)bh * SEQ * HD;
    const float* Vg = g_vt + (size_t)bh * HD * SEQ;

    const unsigned smBase = (unsigned)__cvta_generic_to_shared(sm);

    // per-thread cp.async source/dest for K tile (64x128) and V tile (128x64)
    const int kr = tid >> 1;                 // 0..127? no: see below
    // K tile: 64 rows x 32 float4 chunks = 2048 chunks, 8 per thread
    // thread chunk v = tid + i*256: row = v>>5 (0..63), col4 = (v&31)<<2
    // V tile: 128 rows x 16 chunks = 2048 chunks: row = v>>4, col4 = (v&15)<<2
    (void)kr;

    auto issueK = [&](int kt) {
        if (kt < SEQ/64) {
            const unsigned dstb = smBase + ((OFF_KS + (kt & 1) * KS_ST) << 2);
            const float* src = Kg + (size_t)kt * 64 * HD;
#pragma unroll
            for (int i = 0; i < 8; i++) {
                int v = tid + i * 256;
                int r = v >> 5, cc = (v & 31) << 2;
                cpa16(dstb + ((r * 132 + cc) << 2), src + (size_t)r * HD + cc);
            }
        }
        cp_commit();
    };
    auto issueV = [&](int kt) {
        const unsigned dstb = smBase + (OFF_VT << 2);
#pragma unroll
        for (int i = 0; i < 8; i++) {
            int v = tid + i * 256;
            int dr = v >> 4, cc = (v & 15) << 2;
            cpa16(dstb + ((dr * 68 + cc) << 2), Vg + (size_t)dr * SEQ + kt * 64 + cc);
        }
        cp_commit();
    };

    issueK(0);

    // load Q tile (already tf32 + scaled): 128x128 (plain loads)
#pragma unroll
    for (int i = 0; i < 16; i++) {
        int v = tid + i * 256;
        int r = v >> 5, cc = (v & 31) << 2;
        *(float4*)&Qs[r*132 + cc] = *(const float4*)(Qg + (size_t)r * HD + cc);
    }

    const unsigned qAddr = smBase + (((16*w + ((l>>3)&1)*8 + (l&7))*132 + ((l>>4)<<2)) << 2);
    const unsigned kAddr = smBase + ((OFF_KS + (((l>>4)<<3) + (l&7))*132 + (((l>>3)&1)<<2)) << 2);
    const unsigned vAddr = smBase + ((OFF_VT + (((l>>4)<<3) + (l&7))*68 + (((l>>3)&1)<<2)) << 2);
    const unsigned pAddr = smBase + ((OFF_PS + (16*w + ((l>>3)&1)*8 + (l&7))*68 + ((l>>4)<<2)) << 2);

    float oacc[16][4];
#pragma unroll
    for (int i = 0; i < 16; i++)
#pragma unroll
        for (int v = 0; v < 4; v++) oacc[i][v] = 0.f;
    float mrow[2] = {-1e30f, -1e30f};
    float lrow[2] = {0.f, 0.f};

    for (int kt = 0; kt < SEQ/64; kt++) {
        cp_wait<0>();          // K(kt) complete
        __syncthreads();       // publish K(kt); all warps done PV(kt-1)
        issueV(kt);            // V(kt) overlaps S compute
        issueK(kt + 1);        // K(kt+1) overlaps S/softmax/PV (empty commit if done)

        const unsigned ks_off = (kt & 1) * (KS_ST << 2);

        // S = Q K^T  : warp 16q x 64n, K=128
        float sacc[8][4];
#pragma unroll
        for (int nt = 0; nt < 8; nt++)
#pragma unroll
            for (int v = 0; v < 4; v++) sacc[nt][v] = 0.f;

#pragma unroll
        for (int ks = 0; ks < 16; ks++) {
            unsigned qa[4], kb[4][4];
            ldsm4(qa, qAddr + ((ks*8) << 2));
#pragma unroll
            for (int np = 0; np < 4; np++)
                ldsm4(kb[np], kAddr + ks_off + ((np*16*132 + ks*8) << 2));
#pragma unroll
            for (int nt = 0; nt < 8; nt++)
                mma8(sacc[nt], qa, &kb[nt>>1][(nt&1)*2]);
        }

        // online softmax, warp-local (rows g and g+8)
        float* Ps = sm + OFF_PS;
#pragma unroll
        for (int hh = 0; hh < 2; hh++) {
            float mx = -1e30f;
#pragma unroll
            for (int nt = 0; nt < 8; nt++)
                mx = fmaxf(mx, fmaxf(sacc[nt][2*hh], sacc[nt][2*hh+1]));
            mx = fmaxf(mx, __shfl_xor_sync(0xffffffffu, mx, 1));
            mx = fmaxf(mx, __shfl_xor_sync(0xffffffffu, mx, 2));
            float mn = fmaxf(mrow[hh], mx);
            float fac = __expf(mrow[hh] - mn);
            float rs = 0.f;
#pragma unroll
            for (int nt = 0; nt < 8; nt++) {
                float p0 = __expf(sacc[nt][2*hh]   - mn);
                float p1 = __expf(sacc[nt][2*hh+1] - mn);
                sacc[nt][2*hh] = p0; sacc[nt][2*hh+1] = p1;
                rs += p0 + p1;
                *(float2*)&Ps[(16*w + g + 8*hh)*68 + nt*8 + 2*c] =
                    make_float2(__uint_as_float(f2tf(p0)), __uint_as_float(f2tf(p1)));
            }
            rs += __shfl_xor_sync(0xffffffffu, rs, 1);
            rs += __shfl_xor_sync(0xffffffffu, rs, 2);
            lrow[hh] = lrow[hh] * fac + rs;
            mrow[hh] = mn;
#pragma unroll
            for (int nt = 0; nt < 16; nt++) {
                oacc[nt][2*hh]   *= fac;
                oacc[nt][2*hh+1] *= fac;
            }
        }
        __syncwarp();

        cp_wait<1>();          // V(kt) complete (K(kt+1) may still fly)
        __syncthreads();       // publish V(kt)

        // O += P V : warp 16q x 128d, K=64
#pragma unroll
        for (int ks = 0; ks < 8; ks++) {
            unsigned pa[4];
            ldsm4(pa, pAddr + ((ks*8) << 2));
#pragma unroll
            for (int np = 0; np < 8; np++) {
                unsigned vb[4];
                ldsm4(vb, vAddr + ((np*16*68 + ks*8) << 2));
                mma8(oacc[2*np],   pa, &vb[0]);
                mma8(oacc[2*np+1], pa, &vb[2]);
            }
        }
    }

    // epilogue: divide by l, store merged-head
    const float inv0 = 1.0f / lrow[0], inv1 = 1.0f / lrow[1];
    const int sq = q0 + 16*w + g;
#pragma unroll
    for (int nt = 0; nt < 16; nt++) {
        int d = nt*8 + 2*c;
        float* p0 = g_y + (size_t)(b*SEQ + sq) * DIMX + h*HD + d;
        float* p1 = g_y + (size_t)(b*SEQ + sq + 8) * DIMX + h*HD + d;
        *(float2*)p0 = make_float2(oacc[nt][0]*inv0, oacc[nt][1]*inv0);
        *(float2*)p1 = make_float2(oacc[nt][2]*inv1, oacc[nt][3]*inv1);
    }
}

// ---------------- launch ----------------------------------------------------
extern "C" void kernel_launch(void* const* d_in, const int* in_sizes, int n_in,
                              void* d_out, int out_size)
{
    const float* x     = (const float*)d_in[0];
    const float* wqkv  = (const float*)d_in[1];
    const float* wproj = (const float*)d_in[2];
    const float* qnw   = (const float*)d_in[3];
    const float* knw   = (const float*)d_in[4];
    float* out = (float*)d_out;

    static bool attr_set = false;
    if (!attr_set) {
        cudaFuncSetAttribute(attn_kernel,
                             cudaFuncAttributeMaxDynamicSharedMemorySize,
                             ATTN_SMEM_BYTES);
        cudaFuncSetAttribute(gemm_tf32_kernel,
                             cudaFuncAttributeMaxDynamicSharedMemorySize,
                             GEMM_SMEM_BYTES);
        attr_set = true;
    }

    // 1. QKV projection (tf32 MMA, 3-stage cp.async) with qkv scatter
    gemm_tf32_kernel<<<dim3(3*DIMX/128, TOK/128), 256, GEMM_SMEM_BYTES>>>(
        x, wqkv, nullptr, TOK, 3*DIMX, DIMX, 1);

    // 2. RMSNorm + RoPE (+ q-scale, tf32 round) in place
    norm_rope_kernel<<<(2*BSZ*NH*SEQ)/8, 256>>>(qnw, knw);

    // 3. V transpose -> [bh][d][s] (tf32)
    transpose_v_kernel<<<dim3(SEQ/32, HD/32, BSZ*NH), dim3(32, 8)>>>();

    // 4. attention (tf32 MMA flash, cp.async) -> g_y merged-head
    attn_kernel<<<dim3(SEQ/128, BSZ*NH), 256, ATTN_SMEM_BYTES>>>();

    // 5. output projection (tf32 MMA, 3-stage cp.async)
    gemm_tf32_kernel<<<dim3(DIMX/128, TOK/128), 256, GEMM_SMEM_BYTES>>>(
        nullptr, wproj, out, TOK, DIMX, DIMX, 0);
}

// round 12
// speedup vs baseline: 1.1577x; 1.1577x over previous
#include <cuda_runtime.h>
#include <math.h>

#define BSZ 4
#define SEQ 2048
#define DIMX 2048
#define NH 16
#define HD 128
#define TOK (BSZ*SEQ)   // 8192

// ---------------- scratch (device globals; no cudaMalloc allowed) ----------
__device__ float g_q[BSZ*NH*SEQ*HD];   // [bh][s][d]  fp32 then tf32 after norm
__device__ float g_k[BSZ*NH*SEQ*HD];
__device__ float g_v[BSZ*NH*SEQ*HD];   // fp32
__device__ float g_vt[BSZ*NH*HD*SEQ];  // [bh][d][s]  tf32 bits
__device__ float g_y[TOK*DIMX];        // attention out (tf32 bits)
__device__ float g_xt[TOK*DIMX];       // x in tf32 bits
__device__ float g_wq[3*DIMX*DIMX];    // w_qkv in tf32 bits
__device__ float g_wp[DIMX*DIMX];      // w_proj in tf32 bits

// ---------------- helpers ---------------------------------------------------
__device__ __forceinline__ unsigned f2tf(float x) {
    unsigned u;
    asm("cvt.rna.tf32.f32 %0, %1;" : "=r"(u) : "f"(x));
    return u;
}
__device__ __forceinline__ void ldsm4(unsigned r[4], unsigned addr) {
    asm volatile("ldmatrix.sync.aligned.m8n8.x4.shared.b16 {%0,%1,%2,%3}, [%4];"
                 : "=r"(r[0]), "=r"(r[1]), "=r"(r[2]), "=r"(r[3]) : "r"(addr));
}
__device__ __forceinline__ void mma8(float d[4], const unsigned a[4], const unsigned b[2]) {
    asm volatile("mma.sync.aligned.m16n8k8.row.col.f32.tf32.tf32.f32 "
                 "{%0,%1,%2,%3}, {%4,%5,%6,%7}, {%8,%9}, {%0,%1,%2,%3};"
                 : "+f"(d[0]), "+f"(d[1]), "+f"(d[2]), "+f"(d[3])
                 : "r"(a[0]), "r"(a[1]), "r"(a[2]), "r"(a[3]), "r"(b[0]), "r"(b[1]));
}
__device__ __forceinline__ void cpa16(unsigned s, const void* g) {
    asm volatile("cp.async.cg.shared.global [%0], [%1], 16;" :: "r"(s), "l"(g));
}
__device__ __forceinline__ void cp_commit() {
    asm volatile("cp.async.commit_group;");
}
template<int N> __device__ __forceinline__ void cp_wait() {
    asm volatile("cp.async.wait_group %0;" :: "n"(N));
}

// ---------------- tf32 pre-convert: src fp32 -> global tf32 scratch --------
__global__ void conv_tf32_kernel(const float* __restrict__ src, int which, int n4)
{
    float* dst = (which == 0) ? g_xt : (which == 1) ? g_wq : g_wp;
    int i = blockIdx.x * blockDim.x + threadIdx.x;
    if (i < n4) {
        float4 v = ((const float4*)src)[i];
        ((uint4*)dst)[i] = make_uint4(f2tf(v.x), f2tf(v.y), f2tf(v.z), f2tf(v.w));
    }
}

// ---------------- tf32 GEMM: C[m][n] = sum_k A[m][k]*B[n][k] ----------------
// A,B already tf32 bits. block 128x128, BK=32, 2-stage cp.async, 2 CTAs/SM.
// 8 warps 2(m)x4(n), warp tile 64x32 of m16n8k8.
// mode 1: A=g_xt, B=g_wq, qkv scatter.  mode 0: A=g_y, B=g_wp, store C.
#define GS (128*36)
#define GEMM_SMEM_BYTES (2 * 2 * GS * 4)

__global__ __launch_bounds__(256, 2)
void gemm_tf32_kernel(float* __restrict__ C, int M, int N, int K, int mode)
{
    extern __shared__ __align__(16) float gsm[];
    const float* A = mode ? g_xt : g_y;
    const float* B = mode ? g_wq : g_wp;

    const int tid = threadIdx.x;
    const int l = tid & 31, w = tid >> 5;
    const int wm = w >> 2, wn = w & 3;
    const int m0 = blockIdx.y * 128, n0 = blockIdx.x * 128;

    const int lr = tid >> 3;            // 0..31 (+32*i)
    const int lc = (tid & 7) << 2;      // 0..28

    const float* Ap = A + (size_t)m0 * K;
    const float* Bp = B + (size_t)n0 * K;

    const unsigned smA = (unsigned)__cvta_generic_to_shared(gsm);
    const unsigned smB = smA + 2 * GS * 4;
    const unsigned ldA = smA + ((lr * 36 + lc) << 2);
    const unsigned ldB = smB + ((lr * 36 + lc) << 2);

    const int ntile = K / 32;

    auto issue = [&](int kt) {
        if (kt < ntile) {
            const int st = kt & 1;
            const int ko = kt * 32 + lc;
            const unsigned da = ldA + st * (GS * 4);
            const unsigned db = ldB + st * (GS * 4);
#pragma unroll
            for (int i = 0; i < 4; i++) {
                cpa16(da + i * (32 * 36 * 4), Ap + (size_t)(lr + 32 * i) * K + ko);
                cpa16(db + i * (32 * 36 * 4), Bp + (size_t)(lr + 32 * i) * K + ko);
            }
        }
        cp_commit();
    };

    float acc[4][4][4];
#pragma unroll
    for (int a = 0; a < 4; a++)
#pragma unroll
        for (int b = 0; b < 4; b++)
#pragma unroll
            for (int v = 0; v < 4; v++) acc[a][b][v] = 0.f;

    const unsigned aAddr = smA + (((wm*64 + ((l>>3)&1)*8 + (l&7))*36 + ((l>>4)<<2)) << 2);
    const unsigned bAddr = smB + (((wn*32 + ((l>>4)<<3) + (l&7))*36 + (((l>>3)&1)<<2)) << 2);

    issue(0);
    issue(1);

    for (int kt = 0; kt < ntile; kt++) {
        cp_wait<1>();          // stage kt complete; kt+1 still in flight
        __syncthreads();       // publish stage kt

        const unsigned soff = (kt & 1) * (GS * 4);
#pragma unroll
        for (int ks = 0; ks < 4; ks++) {
            unsigned af[4][4], bf[2][4];
#pragma unroll
            for (int mt = 0; mt < 4; mt++)
                ldsm4(af[mt], aAddr + soff + ((mt*16*36 + ks*8) << 2));
#pragma unroll
            for (int nb = 0; nb < 2; nb++)
                ldsm4(bf[nb], bAddr + soff + ((nb*16*36 + ks*8) << 2));
#pragma unroll
            for (int mt = 0; mt < 4; mt++)
#pragma unroll
                for (int nt = 0; nt < 4; nt++)
                    mma8(acc[mt][nt], af[mt], &bf[nt>>1][(nt&1)*2]);
        }
        __syncthreads();       // all warps done with stage kt's buffer
        issue(kt + 2);         // refill buf kt%2
    }

    const int g = l >> 2, c = l & 3;
    if (mode == 0) {
#pragma unroll
        for (int mt = 0; mt < 4; mt++)
#pragma unroll
            for (int nt = 0; nt < 4; nt++) {
                int m = m0 + wm*64 + mt*16 + g;
                int n = n0 + wn*32 + nt*8 + 2*c;
                *(float2*)&C[(size_t)m*N + n]     = make_float2(acc[mt][nt][0], acc[mt][nt][1]);
                *(float2*)&C[(size_t)(m+8)*N + n] = make_float2(acc[mt][nt][2], acc[mt][nt][3]);
            }
    } else {
        const int which = n0 >> 11;
        const int h = (n0 >> 7) & 15;
        float* dst = (which == 0) ? g_q : (which == 1) ? g_k : g_v;
#pragma unroll
        for (int mt = 0; mt < 4; mt++)
#pragma unroll
            for (int nt = 0; nt < 4; nt++) {
                int m = m0 + wm*64 + mt*16 + g;
                int b_ = m >> 11, s = m & 2047;
                int d = wn*32 + nt*8 + 2*c;
                float* p = dst + (((size_t)(b_*NH + h)*SEQ + s)*HD + d);
                *(float2*)p            = make_float2(acc[mt][nt][0], acc[mt][nt][1]);
                *(float2*)(p + 8*HD)   = make_float2(acc[mt][nt][2], acc[mt][nt][3]);
            }
    }
}

// ---------------- RMSNorm + RoPE on q,k (in place, output tf32 bits) -------
__global__ void norm_rope_kernel(const float* __restrict__ qw,
                                 const float* __restrict__ kw)
{
    const int NROW = BSZ * NH * SEQ;
    int gw = (blockIdx.x * blockDim.x + threadIdx.x) >> 5;
    int lane = threadIdx.x & 31;
    int tensor = (gw >= NROW);
    int row = tensor ? gw - NROW : gw;
    float* base = (tensor ? g_k : g_q) + (size_t)row * HD;
    const float* w = tensor ? kw : qw;
    const int s = row & (SEQ - 1);
    const float qscale = tensor ? 1.0f : 0.08838834764831845f;  // 128^-0.5 on q only

    float4 v = *(const float4*)(base + lane * 4);
    float ss = v.x*v.x + v.y*v.y + v.z*v.z + v.w*v.w;
#pragma unroll
    for (int off = 16; off; off >>= 1)
        ss += __shfl_xor_sync(0xffffffffu, ss, off);
    const float inv = rsqrtf(ss * (1.0f / HD) + 1e-6f);

    const float4 wv = *(const float4*)(w + lane * 4);
    float xv[4];
    xv[0] = v.x * inv * wv.x; xv[1] = v.y * inv * wv.y;
    xv[2] = v.z * inv * wv.z; xv[3] = v.w * inv * wv.w;

    unsigned ov[4];
#pragma unroll
    for (int u = 0; u < 4; u++) {
        float other = __shfl_xor_sync(0xffffffffu, xv[u], 16);
        int i = ((lane & 15) << 2) + u;               // freq index 0..63
        float freq = exp2f(-5.0f * (float)i * (1.0f / 64.0f));  // 32^(-i/64)
        float ang = (float)s * freq;
        float sn, cs;
        sincosf(ang, &sn, &cs);
        float r = (lane < 16) ? (xv[u]*cs - other*sn) : (xv[u]*cs + other*sn);
        ov[u] = f2tf(r * qscale);
    }
    *(uint4*)(base + lane * 4) = make_uint4(ov[0], ov[1], ov[2], ov[3]);
}

// ---------------- V transpose: g_v[bh][s][d] -> g_vt[bh][d][s] (tf32) ------
__global__ void transpose_v_kernel()
{
    __shared__ float t[32][33];
    const int bh = blockIdx.z;
    const int s0 = blockIdx.x * 32, d0 = blockIdx.y * 32;
    const int tx = threadIdx.x, ty = threadIdx.y;
    const float* src = g_v + (size_t)bh * SEQ * HD;
    float* dst = g_vt + (size_t)bh * HD * SEQ;
#pragma unroll
    for (int j = 0; j < 4; j++)
        t[ty + 8*j][tx] = src[(size_t)(s0 + ty + 8*j) * HD + d0 + tx];
    __syncthreads();
#pragma unroll
    for (int j = 0; j < 4; j++)
        dst[(size_t)(d0 + ty + 8*j) * SEQ + s0 + tx] =
            __uint_as_float(f2tf(t[tx][ty + 8*j]));
}

// ---------------- flash attention (tf32 mma, cp.async, Q in registers) -----
// grid (SEQ/128, BSZ*NH), block 256 (8 warps). Warp w owns q rows 16w..16w+15.
// Q fragments hoisted into registers (loop-invariant). K double-buffered.
#define OFF_KS  (128*132)
#define KS_ST   (64*132)
#define OFF_VT  (OFF_KS + 2*KS_ST)
#define OFF_PS  (OFF_VT + 128*68)
#define ATTN_SMEM_BYTES ((OFF_PS + 128*68) * 4)

__global__ __launch_bounds__(256)
void attn_kernel()
{
    extern __shared__ __align__(16) float sm[];
    float* Qs = sm;

    const int tid = threadIdx.x;
    const int w = tid >> 5, l = tid & 31;
    const int g = l >> 2, c = l & 3;
    const int bh = blockIdx.y, b = bh >> 4, h = bh & 15;
    const int q0 = blockIdx.x * 128;
    const float* Qg = g_q + ((size_t)bh * SEQ + q0) * HD;
    const float* Kg = g_k + (size_t)bh * SEQ * HD;
    const float* Vg = g_vt + (size_t)bh * HD * SEQ;

    const unsigned smBase = (unsigned)__cvta_generic_to_shared(sm);

    auto issueK = [&](int kt) {
        if (kt < SEQ/64) {
            const unsigned dstb = smBase + ((OFF_KS + (kt & 1) * KS_ST) << 2);
            const float* src = Kg + (size_t)kt * 64 * HD;
#pragma unroll
            for (int i = 0; i < 8; i++) {
                int v = tid + i * 256;
                int r = v >> 5, cc = (v & 31) << 2;
                cpa16(dstb + ((r * 132 + cc) << 2), src + (size_t)r * HD + cc);
            }
        }
        cp_commit();
    };
    auto issueV = [&](int kt) {
        const unsigned dstb = smBase + (OFF_VT << 2);
#pragma unroll
        for (int i = 0; i < 8; i++) {
            int v = tid + i * 256;
            int dr = v >> 4, cc = (v & 15) << 2;
            cpa16(dstb + ((dr * 68 + cc) << 2), Vg + (size_t)dr * SEQ + kt * 64 + cc);
        }
        cp_commit();
    };

    issueK(0);

    // load Q tile (tf32 + pre-scaled) into smem, then hoist fragments to regs
#pragma unroll
    for (int i = 0; i < 16; i++) {
        int v = tid + i * 256;
        int r = v >> 5, cc = (v & 31) << 2;
        *(float4*)&Qs[r*132 + cc] = *(const float4*)(Qg + (size_t)r * HD + cc);
    }
    __syncthreads();

    const unsigned qAddr = smBase + (((16*w + ((l>>3)&1)*8 + (l&7))*132 + ((l>>4)<<2)) << 2);
    const unsigned kAddr = smBase + ((OFF_KS + (((l>>4)<<3) + (l&7))*132 + (((l>>3)&1)<<2)) << 2);
    const unsigned vAddr = smBase + ((OFF_VT + (((l>>4)<<3) + (l&7))*68 + (((l>>3)&1)<<2)) << 2);
    const unsigned pAddr = smBase + ((OFF_PS + (16*w + ((l>>3)&1)*8 + (l&7))*68 + ((l>>4)<<2)) << 2);

    unsigned qreg[16][4];
#pragma unroll
    for (int ks = 0; ks < 16; ks++)
        ldsm4(qreg[ks], qAddr + ((ks*8) << 2));

    float oacc[16][4];
#pragma unroll
    for (int i = 0; i < 16; i++)
#pragma unroll
        for (int v = 0; v < 4; v++) oacc[i][v] = 0.f;
    float mrow[2] = {-1e30f, -1e30f};
    float lrow[2] = {0.f, 0.f};

    for (int kt = 0; kt < SEQ/64; kt++) {
        cp_wait<0>();          // K(kt) complete
        __syncthreads();       // publish K(kt); all warps done PV(kt-1)
        issueV(kt);            // V(kt) overlaps S compute
        issueK(kt + 1);        // K(kt+1) overlaps S/softmax/PV

        const unsigned ks_off = (kt & 1) * (KS_ST << 2);

        // S = Q K^T  : warp 16q x 64n, K=128
        float sacc[8][4];
#pragma unroll
        for (int nt = 0; nt < 8; nt++)
#pragma unroll
            for (int v = 0; v < 4; v++) sacc[nt][v] = 0.f;

#pragma unroll
        for (int ks = 0; ks < 16; ks++) {
            unsigned kb[4][4];
#pragma unroll
            for (int np = 0; np < 4; np++)
                ldsm4(kb[np], kAddr + ks_off + ((np*16*132 + ks*8) << 2));
#pragma unroll
            for (int nt = 0; nt < 8; nt++)
                mma8(sacc[nt], qreg[ks], &kb[nt>>1][(nt&1)*2]);
        }

        // online softmax, warp-local (rows g and g+8)
        float* Ps = sm + OFF_PS;
#pragma unroll
        for (int hh = 0; hh < 2; hh++) {
            float mx = -1e30f;
#pragma unroll
            for (int nt = 0; nt < 8; nt++)
                mx = fmaxf(mx, fmaxf(sacc[nt][2*hh], sacc[nt][2*hh+1]));
            mx = fmaxf(mx, __shfl_xor_sync(0xffffffffu, mx, 1));
            mx = fmaxf(mx, __shfl_xor_sync(0xffffffffu, mx, 2));
            float mn = fmaxf(mrow[hh], mx);
            float fac = __expf(mrow[hh] - mn);
            float rs = 0.f;
#pragma unroll
            for (int nt = 0; nt < 8; nt++) {
                float p0 = __expf(sacc[nt][2*hh]   - mn);
                float p1 = __expf(sacc[nt][2*hh+1] - mn);
                sacc[nt][2*hh] = p0; sacc[nt][2*hh+1] = p1;
                rs += p0 + p1;
                *(float2*)&Ps[(16*w + g + 8*hh)*68 + nt*8 + 2*c] =
                    make_float2(__uint_as_float(f2tf(p0)), __uint_as_float(f2tf(p1)));
            }
            rs += __shfl_xor_sync(0xffffffffu, rs, 1);
            rs += __shfl_xor_sync(0xffffffffu, rs, 2);
            lrow[hh] = lrow[hh] * fac + rs;
            mrow[hh] = mn;
#pragma unroll
            for (int nt = 0; nt < 16; nt++) {
                oacc[nt][2*hh]   *= fac;
                oacc[nt][2*hh+1] *= fac;
            }
        }
        __syncwarp();

        cp_wait<1>();          // V(kt) complete (K(kt+1) may still fly)
        __syncthreads();       // publish V(kt)

        // O += P V : warp 16q x 128d, K=64
#pragma unroll
        for (int ks = 0; ks < 8; ks++) {
            unsigned pa[4];
            ldsm4(pa, pAddr + ((ks*8) << 2));
#pragma unroll
            for (int np = 0; np < 8; np++) {
                unsigned vb[4];
                ldsm4(vb, vAddr + ((np*16*68 + ks*8) << 2));
                mma8(oacc[2*np],   pa, &vb[0]);
                mma8(oacc[2*np+1], pa, &vb[2]);
            }
        }
    }

    // epilogue: divide by l, store merged-head as tf32 bits (proj reads raw)
    const float inv0 = 1.0f / lrow[0], inv1 = 1.0f / lrow[1];
    const int sq = q0 + 16*w + g;
#pragma unroll
    for (int nt = 0; nt < 16; nt++) {
        int d = nt*8 + 2*c;
        float* p0 = g_y + (size_t)(b*SEQ + sq) * DIMX + h*HD + d;
        float* p1 = g_y + (size_t)(b*SEQ + sq + 8) * DIMX + h*HD + d;
        *(uint2*)p0 = make_uint2(f2tf(oacc[nt][0]*inv0), f2tf(oacc[nt][1]*inv0));
        *(uint2*)p1 = make_uint2(f2tf(oacc[nt][2]*inv1), f2tf(oacc[nt][3]*inv1));
    }
}

// ---------------- launch ----------------------------------------------------
extern "C" void kernel_launch(void* const* d_in, const int* in_sizes, int n_in,
                              void* d_out, int out_size)
{
    const float* x     = (const float*)d_in[0];
    const float* wqkv  = (const float*)d_in[1];
    const float* wproj = (const float*)d_in[2];
    const float* qnw   = (const float*)d_in[3];
    const float* knw   = (const float*)d_in[4];
    float* out = (float*)d_out;

    static bool attr_set = false;
    if (!attr_set) {
        cudaFuncSetAttribute(attn_kernel,
                             cudaFuncAttributeMaxDynamicSharedMemorySize,
                             ATTN_SMEM_BYTES);
        cudaFuncSetAttribute(gemm_tf32_kernel,
                             cudaFuncAttributeMaxDynamicSharedMemorySize,
                             GEMM_SMEM_BYTES);
        attr_set = true;
    }

    // 0. pre-convert inputs to tf32 bits (one RNA rounding, same as before)
    conv_tf32_kernel<<<(TOK*DIMX/4 + 255)/256, 256>>>(x,     0, TOK*DIMX/4);
    conv_tf32_kernel<<<(3*DIMX*DIMX/4 + 255)/256, 256>>>(wqkv, 1, 3*DIMX*DIMX/4);
    conv_tf32_kernel<<<(DIMX*DIMX/4 + 255)/256, 256>>>(wproj, 2, DIMX*DIMX/4);

    // 1. QKV projection (tf32 MMA, 2-stage cp.async, 2 CTAs/SM) + scatter
    gemm_tf32_kernel<<<dim3(3*DIMX/128, TOK/128), 256, GEMM_SMEM_BYTES>>>(
        nullptr, TOK, 3*DIMX, DIMX, 1);

    // 2. RMSNorm + RoPE (+ q-scale, tf32 round) in place
    norm_rope_kernel<<<(2*BSZ*NH*SEQ)/8, 256>>>(qnw, knw);

    // 3. V transpose -> [bh][d][s] (tf32)
    transpose_v_kernel<<<dim3(SEQ/32, HD/32, BSZ*NH), dim3(32, 8)>>>();

    // 4. attention (tf32 MMA flash, Q-in-regs) -> g_y merged-head (tf32 bits)
    attn_kernel<<<dim3(SEQ/128, BSZ*NH), 256, ATTN_SMEM_BYTES>>>();

    // 5. output projection (tf32 MMA)
    gemm_tf32_kernel<<<dim3(DIMX/128, TOK/128), 256, GEMM_SMEM_BYTES>>>(
        out, TOK, DIMX, DIMX, 0);
}

// round 16
// speedup vs baseline: 1.8060x; 1.5600x over previous
#include <cuda_runtime.h>
#include <cuda_fp16.h>
#include <math.h>
#include <stdint.h>

#define BSZ 4
#define SEQ 2048
#define DIMX 2048
#define NH 16
#define HD 128
#define TOK (BSZ*SEQ)   // 8192

// ---------------- scratch (device globals; no cudaMalloc allowed) ----------
__device__ float  g_q [BSZ*NH*SEQ*HD];   // qkv scatter (fp32, pre-norm)
__device__ float  g_k [BSZ*NH*SEQ*HD];
__device__ __half g_qh[BSZ*NH*SEQ*HD];   // post norm+rope, fp16 (+q scale)
__device__ __half g_kh[BSZ*NH*SEQ*HD];
__device__ __half g_vh[BSZ*NH*SEQ*HD];   // v fp16 [bh][s][d]
__device__ __half g_vt[BSZ*NH*HD*SEQ];   // v^T fp16 [bh][d][s]
__device__ __half g_y [TOK*DIMX];        // attention out fp16 [token][dim]
__device__ __half g_xh[TOK*DIMX];        // x fp16
__device__ __half g_wq[3*DIMX*DIMX];     // w_qkv fp16
__device__ __half g_wp[DIMX*DIMX];       // w_proj fp16

// ---------------- helpers ---------------------------------------------------
__device__ __forceinline__ void ldsm4(unsigned r[4], unsigned addr) {
    asm volatile("ldmatrix.sync.aligned.m8n8.x4.shared.b16 {%0,%1,%2,%3}, [%4];"
                 : "=r"(r[0]), "=r"(r[1]), "=r"(r[2]), "=r"(r[3]) : "r"(addr));
}
__device__ __forceinline__ void mma16(float d[4], const unsigned a[4], const unsigned b[2]) {
    asm volatile("mma.sync.aligned.m16n8k16.row.col.f32.f16.f16.f32 "
                 "{%0,%1,%2,%3}, {%4,%5,%6,%7}, {%8,%9}, {%0,%1,%2,%3};"
                 : "+f"(d[0]), "+f"(d[1]), "+f"(d[2]), "+f"(d[3])
                 : "r"(a[0]), "r"(a[1]), "r"(a[2]), "r"(a[3]), "r"(b[0]), "r"(b[1]));
}
__device__ __forceinline__ void cpa16(unsigned s, const void* g) {
    asm volatile("cp.async.cg.shared.global [%0], [%1], 16;" :: "r"(s), "l"(g));
}
__device__ __forceinline__ void cp_commit() {
    asm volatile("cp.async.commit_group;");
}
template<int N> __device__ __forceinline__ void cp_wait() {
    asm volatile("cp.async.wait_group %0;" :: "n"(N));
}
__device__ __forceinline__ unsigned pack_h2(float a, float b) {
    __half2 h = __floats2half2_rn(a, b);
    return *(unsigned*)&h;
}

// ---------------- fp16 pre-convert -----------------------------------------
__global__ void conv_f16_kernel(const float* __restrict__ src, int which, int n4)
{
    __half* dst = (which == 0) ? g_xh : (which == 1) ? g_wq : g_wp;
    int i = blockIdx.x * blockDim.x + threadIdx.x;
    if (i < n4) {
        float4 v = ((const float4*)src)[i];
        ((uint2*)dst)[i] = make_uint2(pack_h2(v.x, v.y), pack_h2(v.z, v.w));
    }
}

// ---------------- fp16 GEMM: C[m][n] = sum_k A[m][k]*B[n][k] ----------------
// block 128x128, BK=32, 2-stage cp.async, 2 CTAs/SM. 8 warps 2(m)x4(n),
// warp tile 64x32 of m16n8k16.
// mode 1: A=g_xh, B=g_wq, qkv scatter (q,k fp32; v fp16).
// mode 0: A=g_y,  B=g_wp, store C fp32.
#define GSH (128*40)                       // halves per stage per matrix
#define GEMM_SMEM_BYTES (2 * 2 * GSH * 2)  // 40960

__global__ __launch_bounds__(256, 2)
void gemm_f16_kernel(float* __restrict__ C, int M, int N, int K, int mode)
{
    extern __shared__ __align__(16) char gsm[];
    const __half* A = mode ? g_xh : g_y;
    const __half* B = mode ? g_wq : g_wp;

    const int tid = threadIdx.x;
    const int l = tid & 31, w = tid >> 5;
    const int wm = w >> 2, wn = w & 3;
    const int m0 = blockIdx.y * 128, n0 = blockIdx.x * 128;

    const int lr = tid >> 2;           // 0..63 (+64)
    const int lc8 = (tid & 3) << 3;    // halves 0,8,16,24

    const __half* Ap = A + (size_t)m0 * K;
    const __half* Bp = B + (size_t)n0 * K;

    const unsigned smA = (unsigned)__cvta_generic_to_shared(gsm);
    const unsigned smB = smA + 2 * GSH * 2;
    const unsigned ldA = smA + ((lr * 40 + lc8) << 1);
    const unsigned ldB = smB + ((lr * 40 + lc8) << 1);

    const int ntile = K / 32;

    auto issue = [&](int kt) {
        if (kt < ntile) {
            const int st = kt & 1;
            const int ko = kt * 32 + lc8;
            const unsigned da = ldA + st * (GSH * 2);
            const unsigned db = ldB + st * (GSH * 2);
#pragma unroll
            for (int i = 0; i < 2; i++) {
                cpa16(da + i * (64 * 40 * 2), Ap + (size_t)(lr + 64 * i) * K + ko);
                cpa16(db + i * (64 * 40 * 2), Bp + (size_t)(lr + 64 * i) * K + ko);
            }
        }
        cp_commit();
    };

    float acc[4][4][4];
#pragma unroll
    for (int a = 0; a < 4; a++)
#pragma unroll
        for (int b = 0; b < 4; b++)
#pragma unroll
            for (int v = 0; v < 4; v++) acc[a][b][v] = 0.f;

    // A frag addr: row = wm*64 + (l&15), col halves = (l>>4)*8
    const unsigned aAddr = smA + (((wm*64 + (l & 15)) * 40 + (l >> 4) * 8) << 1);
    // B frag addr: row = wn*32 + (l&7) + ((l>>4)<<3), col halves = ((l>>3)&1)*8
    const unsigned bAddr = smB + (((wn*32 + (l & 7) + ((l >> 4) << 3)) * 40
                                   + ((l >> 3) & 1) * 8) << 1);

    issue(0);
    issue(1);

    for (int kt = 0; kt < ntile; kt++) {
        cp_wait<1>();
        __syncthreads();

        const unsigned soff = (kt & 1) * (GSH * 2);
#pragma unroll
        for (int ks = 0; ks < 2; ks++) {
            unsigned af[4][4], bf[2][4];
#pragma unroll
            for (int mt = 0; mt < 4; mt++)
                ldsm4(af[mt], aAddr + soff + ((mt*16*40 + ks*16) << 1));
#pragma unroll
            for (int nb = 0; nb < 2; nb++)
                ldsm4(bf[nb], bAddr + soff + ((nb*16*40 + ks*16) << 1));
#pragma unroll
            for (int mt = 0; mt < 4; mt++)
#pragma unroll
                for (int nt = 0; nt < 4; nt++)
                    mma16(acc[mt][nt], af[mt], &bf[nt>>1][(nt&1)*2]);
        }
        __syncthreads();
        issue(kt + 2);
    }

    const int g = l >> 2, c = l & 3;
    if (mode == 0) {
#pragma unroll
        for (int mt = 0; mt < 4; mt++)
#pragma unroll
            for (int nt = 0; nt < 4; nt++) {
                int m = m0 + wm*64 + mt*16 + g;
                int n = n0 + wn*32 + nt*8 + 2*c;
                *(float2*)&C[(size_t)m*N + n]     = make_float2(acc[mt][nt][0], acc[mt][nt][1]);
                *(float2*)&C[(size_t)(m+8)*N + n] = make_float2(acc[mt][nt][2], acc[mt][nt][3]);
            }
    } else {
        const int which = n0 >> 11;
        const int h = (n0 >> 7) & 15;
#pragma unroll
        for (int mt = 0; mt < 4; mt++)
#pragma unroll
            for (int nt = 0; nt < 4; nt++) {
                int m = m0 + wm*64 + mt*16 + g;
                int b_ = m >> 11, s = m & 2047;
                int d = wn*32 + nt*8 + 2*c;
                size_t idx = ((size_t)(b_*NH + h)*SEQ + s)*HD + d;
                if (which == 2) {
                    *(unsigned*)(g_vh + idx)          = pack_h2(acc[mt][nt][0], acc[mt][nt][1]);
                    *(unsigned*)(g_vh + idx + 8*HD)   = pack_h2(acc[mt][nt][2], acc[mt][nt][3]);
                } else {
                    float* dst = (which == 0) ? g_q : g_k;
                    *(float2*)(dst + idx)        = make_float2(acc[mt][nt][0], acc[mt][nt][1]);
                    *(float2*)(dst + idx + 8*HD) = make_float2(acc[mt][nt][2], acc[mt][nt][3]);
                }
            }
    }
}

// ---------------- RMSNorm + RoPE on q,k: fp32 in, fp16 out ------------------
__global__ void norm_rope_kernel(const float* __restrict__ qw,
                                 const float* __restrict__ kw)
{
    const int NROW = BSZ * NH * SEQ;
    int gw = (blockIdx.x * blockDim.x + threadIdx.x) >> 5;
    int lane = threadIdx.x & 31;
    int tensor = (gw >= NROW);
    int row = tensor ? gw - NROW : gw;
    const float* base = (tensor ? g_k : g_q) + (size_t)row * HD;
    __half* outp = (tensor ? g_kh : g_qh) + (size_t)row * HD;
    const float* w = tensor ? kw : qw;
    const int s = row & (SEQ - 1);
    const float qscale = tensor ? 1.0f : 0.08838834764831845f;  // 128^-0.5 on q only

    float4 v = *(const float4*)(base + lane * 4);
    float ss = v.x*v.x + v.y*v.y + v.z*v.z + v.w*v.w;
#pragma unroll
    for (int off = 16; off; off >>= 1)
        ss += __shfl_xor_sync(0xffffffffu, ss, off);
    const float inv = rsqrtf(ss * (1.0f / HD) + 1e-6f);

    const float4 wv = *(const float4*)(w + lane * 4);
    float xv[4];
    xv[0] = v.x * inv * wv.x; xv[1] = v.y * inv * wv.y;
    xv[2] = v.z * inv * wv.z; xv[3] = v.w * inv * wv.w;

    float ov[4];
#pragma unroll
    for (int u = 0; u < 4; u++) {
        float other = __shfl_xor_sync(0xffffffffu, xv[u], 16);
        int i = ((lane & 15) << 2) + u;               // freq index 0..63
        float freq = exp2f(-5.0f * (float)i * (1.0f / 64.0f));  // 32^(-i/64)
        float ang = (float)s * freq;
        float sn, cs;
        sincosf(ang, &sn, &cs);
        float r = (lane < 16) ? (xv[u]*cs - other*sn) : (xv[u]*cs + other*sn);
        ov[u] = r * qscale;
    }
    *(uint2*)(outp + lane * 4) = make_uint2(pack_h2(ov[0], ov[1]), pack_h2(ov[2], ov[3]));
}

// ---------------- V transpose: g_vh[bh][s][d] -> g_vt[bh][d][s] -------------
__global__ void transpose_v_kernel()
{
    __shared__ __half t[32][34];
    const int bh = blockIdx.z;
    const int s0 = blockIdx.x * 32, d0 = blockIdx.y * 32;
    const int tx = threadIdx.x, ty = threadIdx.y;
    const __half* src = g_vh + (size_t)bh * SEQ * HD;
    __half* dst = g_vt + (size_t)bh * HD * SEQ;
#pragma unroll
    for (int j = 0; j < 4; j++)
        t[ty + 8*j][tx] = src[(size_t)(s0 + ty + 8*j) * HD + d0 + tx];
    __syncthreads();
#pragma unroll
    for (int j = 0; j < 4; j++)
        dst[(size_t)(d0 + ty + 8*j) * SEQ + s0 + tx] = t[tx][ty + 8*j];
}

// ---------------- flash attention (fp16 mma, cp.async, Q in registers) ------
// grid (SEQ/128, BSZ*NH), block 256 (8 warps). Warp w owns q rows 16w..16w+15.
// smem halves: Qs[128*136] | Ks[2][64*136] | Vt[128*72] | Ps[128*72]
#define OFF_KS  (128*136)
#define KS_ST   (64*136)
#define OFF_VT  (OFF_KS + 2*KS_ST)
#define OFF_PS  (OFF_VT + 128*72)
#define ATTN_SMEM_BYTES ((OFF_PS + 128*72) * 2)

__global__ __launch_bounds__(256)
void attn_kernel()
{
    extern __shared__ __align__(16) __half sh[];

    const int tid = threadIdx.x;
    const int w = tid >> 5, l = tid & 31;
    const int g = l >> 2, c = l & 3;
    const int bh = blockIdx.y, b = bh >> 4, h = bh & 15;
    const int q0 = blockIdx.x * 128;
    const __half* Qg = g_qh + ((size_t)bh * SEQ + q0) * HD;
    const __half* Kg = g_kh + (size_t)bh * SEQ * HD;
    const __half* Vg = g_vt + (size_t)bh * HD * SEQ;

    const unsigned smBase = (unsigned)__cvta_generic_to_shared(sh);

    auto issueK = [&](int kt) {
        if (kt < SEQ/64) {
            const unsigned dstb = smBase + ((OFF_KS + (kt & 1) * KS_ST) << 1);
            const __half* src = Kg + (size_t)kt * 64 * HD;
#pragma unroll
            for (int i = 0; i < 4; i++) {          // 64 rows x 16 chunks
                int v = tid + i * 256;
                int r = v >> 4, c8 = (v & 15) << 3;
                cpa16(dstb + ((r * 136 + c8) << 1), src + (size_t)r * HD + c8);
            }
        }
        cp_commit();
    };
    auto issueV = [&](int kt) {
        const unsigned dstb = smBase + (OFF_VT << 1);
#pragma unroll
        for (int i = 0; i < 4; i++) {              // 128 rows x 8 chunks
            int v = tid + i * 256;
            int dr = v >> 3, c8 = (v & 7) << 3;
            cpa16(dstb + ((dr * 72 + c8) << 1), Vg + (size_t)dr * SEQ + kt * 64 + c8);
        }
        cp_commit();
    };

    issueK(0);

    // load Q tile 128x128 halves
#pragma unroll
    for (int i = 0; i < 8; i++) {
        int v = tid + i * 256;
        int r = v >> 4, c8 = (v & 15) << 3;
        *(uint4*)&sh[r*136 + c8] = *(const uint4*)(Qg + (size_t)r * HD + c8);
    }
    __syncthreads();

    // A-frag: row = 16w + (l&15), col halves = (l>>4)*8
    const unsigned qAddr = smBase + (((16*w + (l & 15)) * 136 + (l >> 4) * 8) << 1);
    // B-frag on K: row = (l&7)+((l>>4)<<3), col = ((l>>3)&1)*8
    const unsigned kAddr = smBase + ((OFF_KS + ((l & 7) + ((l >> 4) << 3)) * 136
                                      + ((l >> 3) & 1) * 8) << 1);
    const unsigned vAddr = smBase + ((OFF_VT + ((l & 7) + ((l >> 4) << 3)) * 72
                                      + ((l >> 3) & 1) * 8) << 1);
    const unsigned pAddr = smBase + ((OFF_PS + (16*w + (l & 15)) * 72 + (l >> 4) * 8) << 1);

    unsigned qreg[8][4];
#pragma unroll
    for (int ks = 0; ks < 8; ks++)
        ldsm4(qreg[ks], qAddr + ((ks * 16) << 1));

    float oacc[16][4];
#pragma unroll
    for (int i = 0; i < 16; i++)
#pragma unroll
        for (int v = 0; v < 4; v++) oacc[i][v] = 0.f;
    float mrow[2] = {-1e30f, -1e30f};
    float lrow[2] = {0.f, 0.f};

    for (int kt = 0; kt < SEQ/64; kt++) {
        cp_wait<0>();
        __syncthreads();
        issueV(kt);
        issueK(kt + 1);

        const unsigned ks_off = (kt & 1) * (KS_ST << 1);

        // S = Q K^T : warp 16q x 64n, K=128 (8 k16 steps)
        float sacc[8][4];
#pragma unroll
        for (int nt = 0; nt < 8; nt++)
#pragma unroll
            for (int v = 0; v < 4; v++) sacc[nt][v] = 0.f;

#pragma unroll
        for (int ks = 0; ks < 8; ks++) {
            unsigned kb[4][4];
#pragma unroll
            for (int np = 0; np < 4; np++)
                ldsm4(kb[np], kAddr + ks_off + ((np*16*136 + ks*16) << 1));
#pragma unroll
            for (int nt = 0; nt < 8; nt++)
                mma16(sacc[nt], qreg[ks], &kb[nt>>1][(nt&1)*2]);
        }

        // online softmax, warp-local (rows g and g+8)
        __half* Ps = sh + OFF_PS;
#pragma unroll
        for (int hh = 0; hh < 2; hh++) {
            float mx = -1e30f;
#pragma unroll
            for (int nt = 0; nt < 8; nt++)
                mx = fmaxf(mx, fmaxf(sacc[nt][2*hh], sacc[nt][2*hh+1]));
            mx = fmaxf(mx, __shfl_xor_sync(0xffffffffu, mx, 1));
            mx = fmaxf(mx, __shfl_xor_sync(0xffffffffu, mx, 2));
            float mn = fmaxf(mrow[hh], mx);
            float fac = __expf(mrow[hh] - mn);
            float rs = 0.f;
#pragma unroll
            for (int nt = 0; nt < 8; nt++) {
                float p0 = __expf(sacc[nt][2*hh]   - mn);
                float p1 = __expf(sacc[nt][2*hh+1] - mn);
                rs += p0 + p1;
                *(unsigned*)&Ps[(16*w + g + 8*hh)*72 + nt*8 + 2*c] = pack_h2(p0, p1);
            }
            rs += __shfl_xor_sync(0xffffffffu, rs, 1);
            rs += __shfl_xor_sync(0xffffffffu, rs, 2);
            lrow[hh] = lrow[hh] * fac + rs;
            mrow[hh] = mn;
#pragma unroll
            for (int nt = 0; nt < 16; nt++) {
                oacc[nt][2*hh]   *= fac;
                oacc[nt][2*hh+1] *= fac;
            }
        }
        __syncwarp();

        cp_wait<1>();
        __syncthreads();

        // O += P V : warp 16q x 128d, K=64 (4 k16 steps)
#pragma unroll
        for (int ks = 0; ks < 4; ks++) {
            unsigned pa[4];
            ldsm4(pa, pAddr + ((ks * 16) << 1));
#pragma unroll
            for (int np = 0; np < 8; np++) {
                unsigned vb[4];
                ldsm4(vb, vAddr + ((np*16*72 + ks*16) << 1));
                mma16(oacc[2*np],   pa, &vb[0]);
                mma16(oacc[2*np+1], pa, &vb[2]);
            }
        }
    }

    // epilogue: divide by l, store merged-head fp16 (proj reads g_y)
    const float inv0 = 1.0f / lrow[0], inv1 = 1.0f / lrow[1];
    const int sq = q0 + 16*w + g;
#pragma unroll
    for (int nt = 0; nt < 16; nt++) {
        int d = nt*8 + 2*c;
        __half* p0 = g_y + (size_t)(b*SEQ + sq) * DIMX + h*HD + d;
        __half* p1 = g_y + (size_t)(b*SEQ + sq + 8) * DIMX + h*HD + d;
        *(unsigned*)p0 = pack_h2(oacc[nt][0]*inv0, oacc[nt][1]*inv0);
        *(unsigned*)p1 = pack_h2(oacc[nt][2]*inv1, oacc[nt][3]*inv1);
    }
}

// ---------------- launch ----------------------------------------------------
extern "C" void kernel_launch(void* const* d_in, const int* in_sizes, int n_in,
                              void* d_out, int out_size)
{
    const float* x     = (const float*)d_in[0];
    const float* wqkv  = (const float*)d_in[1];
    const float* wproj = (const float*)d_in[2];
    const float* qnw   = (const float*)d_in[3];
    const float* knw   = (const float*)d_in[4];
    float* out = (float*)d_out;

    static bool attr_set = false;
    if (!attr_set) {
        cudaFuncSetAttribute(attn_kernel,
                             cudaFuncAttributeMaxDynamicSharedMemorySize,
                             ATTN_SMEM_BYTES);
        cudaFuncSetAttribute(gemm_f16_kernel,
                             cudaFuncAttributeMaxDynamicSharedMemorySize,
                             GEMM_SMEM_BYTES);
        attr_set = true;
    }

    // 0. pre-convert inputs to fp16
    conv_f16_kernel<<<(TOK*DIMX/4 + 255)/256, 256>>>(x,     0, TOK*DIMX/4);
    conv_f16_kernel<<<(3*DIMX*DIMX/4 + 255)/256, 256>>>(wqkv, 1, 3*DIMX*DIMX/4);
    conv_f16_kernel<<<(DIMX*DIMX/4 + 255)/256, 256>>>(wproj, 2, DIMX*DIMX/4);

    // 1. QKV projection (fp16 MMA) + scatter (q,k fp32; v fp16)
    gemm_f16_kernel<<<dim3(3*DIMX/128, TOK/128), 256, GEMM_SMEM_BYTES>>>(
        nullptr, TOK, 3*DIMX, DIMX, 1);

    // 2. RMSNorm + RoPE (+ q-scale) fp32 -> fp16
    norm_rope_kernel<<<(2*BSZ*NH*SEQ)/8, 256>>>(qnw, knw);

    // 3. V transpose -> [bh][d][s] fp16
    transpose_v_kernel<<<dim3(SEQ/32, HD/32, BSZ*NH), dim3(32, 8)>>>();

    // 4. attention (fp16 MMA flash, Q-in-regs) -> g_y fp16
    attn_kernel<<<dim3(SEQ/128, BSZ*NH), 256, ATTN_SMEM_BYTES>>>();

    // 5. output projection (fp16 MMA) -> fp32 out
    gemm_f16_kernel<<<dim3(DIMX/128, TOK/128), 256, GEMM_SMEM_BYTES>>>(
        out, TOK, DIMX, DIMX, 0);
}

// round 17
// speedup vs baseline: 2.0527x; 1.1366x over previous
#include <cuda_runtime.h>
#include <cuda_fp16.h>
#include <math.h>
#include <stdint.h>

#define BSZ 4
#define SEQ 2048
#define DIMX 2048
#define NH 16
#define HD 128
#define TOK (BSZ*SEQ)   // 8192

// ---------------- scratch (device globals; no cudaMalloc allowed) ----------
__device__ float  g_q [BSZ*NH*SEQ*HD];   // qkv scatter (fp32, pre-norm)
__device__ float  g_k [BSZ*NH*SEQ*HD];
__device__ __half g_qh[BSZ*NH*SEQ*HD];   // post norm+rope, fp16 (+q scale)
__device__ __half g_kh[BSZ*NH*SEQ*HD];
__device__ __half g_vh[BSZ*NH*SEQ*HD];   // v fp16 [bh][s][d]
__device__ __half g_vt[BSZ*NH*HD*SEQ];   // v^T fp16 [bh][d][s]
__device__ __half g_y [TOK*DIMX];        // attention out fp16 [token][dim]
__device__ __half g_xh[TOK*DIMX];        // x fp16
__device__ __half g_wq[3*DIMX*DIMX];     // w_qkv fp16
__device__ __half g_wp[DIMX*DIMX];       // w_proj fp16

// ---------------- helpers ---------------------------------------------------
__device__ __forceinline__ void ldsm4(unsigned r[4], unsigned addr) {
    asm volatile("ldmatrix.sync.aligned.m8n8.x4.shared.b16 {%0,%1,%2,%3}, [%4];"
                 : "=r"(r[0]), "=r"(r[1]), "=r"(r[2]), "=r"(r[3]) : "r"(addr));
}
__device__ __forceinline__ void mma16(float d[4], const unsigned a[4], const unsigned b[2]) {
    asm volatile("mma.sync.aligned.m16n8k16.row.col.f32.f16.f16.f32 "
                 "{%0,%1,%2,%3}, {%4,%5,%6,%7}, {%8,%9}, {%0,%1,%2,%3};"
                 : "+f"(d[0]), "+f"(d[1]), "+f"(d[2]), "+f"(d[3])
                 : "r"(a[0]), "r"(a[1]), "r"(a[2]), "r"(a[3]), "r"(b[0]), "r"(b[1]));
}
__device__ __forceinline__ void cpa16(unsigned s, const void* g) {
    asm volatile("cp.async.cg.shared.global [%0], [%1], 16;" :: "r"(s), "l"(g));
}
__device__ __forceinline__ void cp_commit() {
    asm volatile("cp.async.commit_group;");
}
template<int N> __device__ __forceinline__ void cp_wait() {
    asm volatile("cp.async.wait_group %0;" :: "n"(N));
}
__device__ __forceinline__ unsigned pack_h2(float a, float b) {
    __half2 h = __floats2half2_rn(a, b);
    return *(unsigned*)&h;
}

// ---------------- fp16 pre-convert -----------------------------------------
__global__ void conv_f16_kernel(const float* __restrict__ src, int which, int n4)
{
    __half* dst = (which == 0) ? g_xh : (which == 1) ? g_wq : g_wp;
    int i = blockIdx.x * blockDim.x + threadIdx.x;
    if (i < n4) {
        float4 v = ((const float4*)src)[i];
        ((uint2*)dst)[i] = make_uint2(pack_h2(v.x, v.y), pack_h2(v.z, v.w));
    }
}

// ---------------- fp16 GEMM: C[m][n] = sum_k A[m][k]*B[n][k] ----------------
// block 128x128, BK=64, 3-stage cp.async ring, ONE barrier per k-tile,
// 2 CTAs/SM. 8 warps 2(m)x4(n), warp tile 64x32 of m16n8k16.
// mode 1: A=g_xh, B=g_wq, qkv scatter (q,k fp32; v fp16).
// mode 0: A=g_y,  B=g_wp, store C fp32.
#define GSH (128*72)                       // halves per stage per matrix
#define GEMM_SMEM_BYTES (3 * 2 * GSH * 2)  // 110592

__global__ __launch_bounds__(256, 2)
void gemm_f16_kernel(float* __restrict__ C, int M, int N, int K, int mode)
{
    extern __shared__ __align__(16) char gsm[];
    const __half* A = mode ? g_xh : g_y;
    const __half* B = mode ? g_wq : g_wp;

    const int tid = threadIdx.x;
    const int l = tid & 31, w = tid >> 5;
    const int wm = w >> 2, wn = w & 3;
    const int m0 = blockIdx.y * 128, n0 = blockIdx.x * 128;

    const int lr  = tid >> 3;          // 0..31 (+32*i)
    const int lc8 = (tid & 7) << 3;    // halves 0..56

    const __half* Ap = A + (size_t)m0 * K;
    const __half* Bp = B + (size_t)n0 * K;

    const unsigned smA = (unsigned)__cvta_generic_to_shared(gsm);
    const unsigned smB = smA + 3 * GSH * 2;
    const unsigned ldA = smA + ((lr * 72 + lc8) << 1);
    const unsigned ldB = smB + ((lr * 72 + lc8) << 1);

    const int ntile = K / 64;          // 32

    auto issue = [&](int kt) {
        if (kt < ntile) {
            const int st = kt % 3;
            const int ko = kt * 64 + lc8;
            const unsigned da = ldA + st * (GSH * 2);
            const unsigned db = ldB + st * (GSH * 2);
#pragma unroll
            for (int i = 0; i < 4; i++) {
                cpa16(da + i * (32 * 72 * 2), Ap + (size_t)(lr + 32 * i) * K + ko);
                cpa16(db + i * (32 * 72 * 2), Bp + (size_t)(lr + 32 * i) * K + ko);
            }
        }
        cp_commit();
    };

    float acc[4][4][4];
#pragma unroll
    for (int a = 0; a < 4; a++)
#pragma unroll
        for (int b = 0; b < 4; b++)
#pragma unroll
            for (int v = 0; v < 4; v++) acc[a][b][v] = 0.f;

    // A frag addr: row = wm*64 + (l&15), col halves = (l>>4)*8
    const unsigned aAddr = smA + (((wm*64 + (l & 15)) * 72 + (l >> 4) * 8) << 1);
    // B frag addr: row = wn*32 + (l&7) + ((l>>4)<<3), col halves = ((l>>3)&1)*8
    const unsigned bAddr = smB + (((wn*32 + (l & 7) + ((l >> 4) << 3)) * 72
                                   + ((l >> 3) & 1) * 8) << 1);

    issue(0);
    issue(1);

    for (int kt = 0; kt < ntile; kt++) {
        cp_wait<1>();          // stage kt landed (kt+1 may still fly)
        __syncthreads();       // publish kt; all warps finished kt-1
        issue(kt + 2);         // overwrites buf (kt+2)%3 == (kt-1)%3 — safe

        const unsigned soff = (kt % 3) * (GSH * 2);
#pragma unroll
        for (int ks = 0; ks < 4; ks++) {
            unsigned af[4][4], bf[2][4];
#pragma unroll
            for (int mt = 0; mt < 4; mt++)
                ldsm4(af[mt], aAddr + soff + ((mt*16*72 + ks*16) << 1));
#pragma unroll
            for (int nb = 0; nb < 2; nb++)
                ldsm4(bf[nb], bAddr + soff + ((nb*16*72 + ks*16) << 1));
#pragma unroll
            for (int mt = 0; mt < 4; mt++)
#pragma unroll
                for (int nt = 0; nt < 4; nt++)
                    mma16(acc[mt][nt], af[mt], &bf[nt>>1][(nt&1)*2]);
        }
    }

    const int g = l >> 2, c = l & 3;
    if (mode == 0) {
#pragma unroll
        for (int mt = 0; mt < 4; mt++)
#pragma unroll
            for (int nt = 0; nt < 4; nt++) {
                int m = m0 + wm*64 + mt*16 + g;
                int n = n0 + wn*32 + nt*8 + 2*c;
                *(float2*)&C[(size_t)m*N + n]     = make_float2(acc[mt][nt][0], acc[mt][nt][1]);
                *(float2*)&C[(size_t)(m+8)*N + n] = make_float2(acc[mt][nt][2], acc[mt][nt][3]);
            }
    } else {
        const int which = n0 >> 11;
        const int h = (n0 >> 7) & 15;
#pragma unroll
        for (int mt = 0; mt < 4; mt++)
#pragma unroll
            for (int nt = 0; nt < 4; nt++) {
                int m = m0 + wm*64 + mt*16 + g;
                int b_ = m >> 11, s = m & 2047;
                int d = wn*32 + nt*8 + 2*c;
                size_t idx = ((size_t)(b_*NH + h)*SEQ + s)*HD + d;
                if (which == 2) {
                    *(unsigned*)(g_vh + idx)          = pack_h2(acc[mt][nt][0], acc[mt][nt][1]);
                    *(unsigned*)(g_vh + idx + 8*HD)   = pack_h2(acc[mt][nt][2], acc[mt][nt][3]);
                } else {
                    float* dst = (which == 0) ? g_q : g_k;
                    *(float2*)(dst + idx)        = make_float2(acc[mt][nt][0], acc[mt][nt][1]);
                    *(float2*)(dst + idx + 8*HD) = make_float2(acc[mt][nt][2], acc[mt][nt][3]);
                }
            }
    }
}

// ---------------- RMSNorm + RoPE on q,k: fp32 in, fp16 out ------------------
__global__ void norm_rope_kernel(const float* __restrict__ qw,
                                 const float* __restrict__ kw)
{
    const int NROW = BSZ * NH * SEQ;
    int gw = (blockIdx.x * blockDim.x + threadIdx.x) >> 5;
    int lane = threadIdx.x & 31;
    int tensor = (gw >= NROW);
    int row = tensor ? gw - NROW : gw;
    const float* base = (tensor ? g_k : g_q) + (size_t)row * HD;
    __half* outp = (tensor ? g_kh : g_qh) + (size_t)row * HD;
    const float* w = tensor ? kw : qw;
    const int s = row & (SEQ - 1);
    const float qscale = tensor ? 1.0f : 0.08838834764831845f;  // 128^-0.5 on q only

    float4 v = *(const float4*)(base + lane * 4);
    float ss = v.x*v.x + v.y*v.y + v.z*v.z + v.w*v.w;
#pragma unroll
    for (int off = 16; off; off >>= 1)
        ss += __shfl_xor_sync(0xffffffffu, ss, off);
    const float inv = rsqrtf(ss * (1.0f / HD) + 1e-6f);

    const float4 wv = *(const float4*)(w + lane * 4);
    float xv[4];
    xv[0] = v.x * inv * wv.x; xv[1] = v.y * inv * wv.y;
    xv[2] = v.z * inv * wv.z; xv[3] = v.w * inv * wv.w;

    float ov[4];
#pragma unroll
    for (int u = 0; u < 4; u++) {
        float other = __shfl_xor_sync(0xffffffffu, xv[u], 16);
        int i = ((lane & 15) << 2) + u;               // freq index 0..63
        float freq = exp2f(-5.0f * (float)i * (1.0f / 64.0f));  // 32^(-i/64)
        float ang = (float)s * freq;
        float sn, cs;
        sincosf(ang, &sn, &cs);
        float r = (lane < 16) ? (xv[u]*cs - other*sn) : (xv[u]*cs + other*sn);
        ov[u] = r * qscale;
    }
    *(uint2*)(outp + lane * 4) = make_uint2(pack_h2(ov[0], ov[1]), pack_h2(ov[2], ov[3]));
}

// ---------------- V transpose: g_vh[bh][s][d] -> g_vt[bh][d][s] -------------
__global__ void transpose_v_kernel()
{
    __shared__ __half t[32][34];
    const int bh = blockIdx.z;
    const int s0 = blockIdx.x * 32, d0 = blockIdx.y * 32;
    const int tx = threadIdx.x, ty = threadIdx.y;
    const __half* src = g_vh + (size_t)bh * SEQ * HD;
    __half* dst = g_vt + (size_t)bh * HD * SEQ;
#pragma unroll
    for (int j = 0; j < 4; j++)
        t[ty + 8*j][tx] = src[(size_t)(s0 + ty + 8*j) * HD + d0 + tx];
    __syncthreads();
#pragma unroll
    for (int j = 0; j < 4; j++)
        dst[(size_t)(d0 + ty + 8*j) * SEQ + s0 + tx] = t[tx][ty + 8*j];
}

// ---------------- flash attention (fp16 mma, cp.async, Q in registers) ------
// grid (SEQ/128, BSZ*NH), block 256 (8 warps). Warp w owns q rows 16w..16w+15.
// smem halves: Qs[128*136] | Ks[2][64*136] | Vt[128*72] | Ps[128*72]
#define OFF_KS  (128*136)
#define KS_ST   (64*136)
#define OFF_VT  (OFF_KS + 2*KS_ST)
#define OFF_PS  (OFF_VT + 128*72)
#define ATTN_SMEM_BYTES ((OFF_PS + 128*72) * 2)

__global__ __launch_bounds__(256)
void attn_kernel()
{
    extern __shared__ __align__(16) __half sh[];

    const int tid = threadIdx.x;
    const int w = tid >> 5, l = tid & 31;
    const int g = l >> 2, c = l & 3;
    const int bh = blockIdx.y, b = bh >> 4, h = bh & 15;
    const int q0 = blockIdx.x * 128;
    const __half* Qg = g_qh + ((size_t)bh * SEQ + q0) * HD;
    const __half* Kg = g_kh + (size_t)bh * SEQ * HD;
    const __half* Vg = g_vt + (size_t)bh * HD * SEQ;

    const unsigned smBase = (unsigned)__cvta_generic_to_shared(sh);

    auto issueK = [&](int kt) {
        if (kt < SEQ/64) {
            const unsigned dstb = smBase + ((OFF_KS + (kt & 1) * KS_ST) << 1);
            const __half* src = Kg + (size_t)kt * 64 * HD;
#pragma unroll
            for (int i = 0; i < 4; i++) {          // 64 rows x 16 chunks
                int v = tid + i * 256;
                int r = v >> 4, c8 = (v & 15) << 3;
                cpa16(dstb + ((r * 136 + c8) << 1), src + (size_t)r * HD + c8);
            }
        }
        cp_commit();
    };
    auto issueV = [&](int kt) {
        const unsigned dstb = smBase + (OFF_VT << 1);
#pragma unroll
        for (int i = 0; i < 4; i++) {              // 128 rows x 8 chunks
            int v = tid + i * 256;
            int dr = v >> 3, c8 = (v & 7) << 3;
            cpa16(dstb + ((dr * 72 + c8) << 1), Vg + (size_t)dr * SEQ + kt * 64 + c8);
        }
        cp_commit();
    };

    issueK(0);

    // load Q tile 128x128 halves
#pragma unroll
    for (int i = 0; i < 8; i++) {
        int v = tid + i * 256;
        int r = v >> 4, c8 = (v & 15) << 3;
        *(uint4*)&sh[r*136 + c8] = *(const uint4*)(Qg + (size_t)r * HD + c8);
    }
    __syncthreads();

    // A-frag: row = 16w + (l&15), col halves = (l>>4)*8
    const unsigned qAddr = smBase + (((16*w + (l & 15)) * 136 + (l >> 4) * 8) << 1);
    // B-frag on K: row = (l&7)+((l>>4)<<3), col = ((l>>3)&1)*8
    const unsigned kAddr = smBase + ((OFF_KS + ((l & 7) + ((l >> 4) << 3)) * 136
                                      + ((l >> 3) & 1) * 8) << 1);
    const unsigned vAddr = smBase + ((OFF_VT + ((l & 7) + ((l >> 4) << 3)) * 72
                                      + ((l >> 3) & 1) * 8) << 1);
    const unsigned pAddr = smBase + ((OFF_PS + (16*w + (l & 15)) * 72 + (l >> 4) * 8) << 1);

    unsigned qreg[8][4];
#pragma unroll
    for (int ks = 0; ks < 8; ks++)
        ldsm4(qreg[ks], qAddr + ((ks * 16) << 1));

    float oacc[16][4];
#pragma unroll
    for (int i = 0; i < 16; i++)
#pragma unroll
        for (int v = 0; v < 4; v++) oacc[i][v] = 0.f;
    float mrow[2] = {-1e30f, -1e30f};
    float lrow[2] = {0.f, 0.f};

    for (int kt = 0; kt < SEQ/64; kt++) {
        cp_wait<0>();
        __syncthreads();
        issueV(kt);
        issueK(kt + 1);

        const unsigned ks_off = (kt & 1) * (KS_ST << 1);

        // S = Q K^T : warp 16q x 64n, K=128 (8 k16 steps)
        float sacc[8][4];
#pragma unroll
        for (int nt = 0; nt < 8; nt++)
#pragma unroll
            for (int v = 0; v < 4; v++) sacc[nt][v] = 0.f;

#pragma unroll
        for (int ks = 0; ks < 8; ks++) {
            unsigned kb[4][4];
#pragma unroll
            for (int np = 0; np < 4; np++)
                ldsm4(kb[np], kAddr + ks_off + ((np*16*136 + ks*16) << 1));
#pragma unroll
            for (int nt = 0; nt < 8; nt++)
                mma16(sacc[nt], qreg[ks], &kb[nt>>1][(nt&1)*2]);
        }

        // online softmax, warp-local (rows g and g+8)
        __half* Ps = sh + OFF_PS;
#pragma unroll
        for (int hh = 0; hh < 2; hh++) {
            float mx = -1e30f;
#pragma unroll
            for (int nt = 0; nt < 8; nt++)
                mx = fmaxf(mx, fmaxf(sacc[nt][2*hh], sacc[nt][2*hh+1]));
            mx = fmaxf(mx, __shfl_xor_sync(0xffffffffu, mx, 1));
            mx = fmaxf(mx, __shfl_xor_sync(0xffffffffu, mx, 2));
            float mn = fmaxf(mrow[hh], mx);
            float fac = __expf(mrow[hh] - mn);
            float rs = 0.f;
#pragma unroll
            for (int nt = 0; nt < 8; nt++) {
                float p0 = __expf(sacc[nt][2*hh]   - mn);
                float p1 = __expf(sacc[nt][2*hh+1] - mn);
                rs += p0 + p1;
                *(unsigned*)&Ps[(16*w + g + 8*hh)*72 + nt*8 + 2*c] = pack_h2(p0, p1);
            }
            rs += __shfl_xor_sync(0xffffffffu, rs, 1);
            rs += __shfl_xor_sync(0xffffffffu, rs, 2);
            lrow[hh] = lrow[hh] * fac + rs;
            mrow[hh] = mn;
#pragma unroll
            for (int nt = 0; nt < 16; nt++) {
                oacc[nt][2*hh]   *= fac;
                oacc[nt][2*hh+1] *= fac;
            }
        }
        __syncwarp();

        cp_wait<1>();
        __syncthreads();

        // O += P V : warp 16q x 128d, K=64 (4 k16 steps)
#pragma unroll
        for (int ks = 0; ks < 4; ks++) {
            unsigned pa[4];
            ldsm4(pa, pAddr + ((ks * 16) << 1));
#pragma unroll
            for (int np = 0; np < 8; np++) {
                unsigned vb[4];
                ldsm4(vb, vAddr + ((np*16*72 + ks*16) << 1));
                mma16(oacc[2*np],   pa, &vb[0]);
                mma16(oacc[2*np+1], pa, &vb[2]);
            }
        }
    }

    // epilogue: divide by l, store merged-head fp16 (proj reads g_y)
    const float inv0 = 1.0f / lrow[0], inv1 = 1.0f / lrow[1];
    const int sq = q0 + 16*w + g;
#pragma unroll
    for (int nt = 0; nt < 16; nt++) {
        int d = nt*8 + 2*c;
        __half* p0 = g_y + (size_t)(b*SEQ + sq) * DIMX + h*HD + d;
        __half* p1 = g_y + (size_t)(b*SEQ + sq + 8) * DIMX + h*HD + d;
        *(unsigned*)p0 = pack_h2(oacc[nt][0]*inv0, oacc[nt][1]*inv0);
        *(unsigned*)p1 = pack_h2(oacc[nt][2]*inv1, oacc[nt][3]*inv1);
    }
}

// ---------------- launch ----------------------------------------------------
extern "C" void kernel_launch(void* const* d_in, const int* in_sizes, int n_in,
                              void* d_out, int out_size)
{
    const float* x     = (const float*)d_in[0];
    const float* wqkv  = (const float*)d_in[1];
    const float* wproj = (const float*)d_in[2];
    const float* qnw   = (const float*)d_in[3];
    const float* knw   = (const float*)d_in[4];
    float* out = (float*)d_out;

    static bool attr_set = false;
    if (!attr_set) {
        cudaFuncSetAttribute(attn_kernel,
                             cudaFuncAttributeMaxDynamicSharedMemorySize,
                             ATTN_SMEM_BYTES);
        cudaFuncSetAttribute(gemm_f16_kernel,
                             cudaFuncAttributeMaxDynamicSharedMemorySize,
                             GEMM_SMEM_BYTES);
        attr_set = true;
    }

    // 0. pre-convert inputs to fp16
    conv_f16_kernel<<<(TOK*DIMX/4 + 255)/256, 256>>>(x,     0, TOK*DIMX/4);
    conv_f16_kernel<<<(3*DIMX*DIMX/4 + 255)/256, 256>>>(wqkv, 1, 3*DIMX*DIMX/4);
    conv_f16_kernel<<<(DIMX*DIMX/4 + 255)/256, 256>>>(wproj, 2, DIMX*DIMX/4);

    // 1. QKV projection (fp16 MMA, BK=64, 3-stage) + scatter
    gemm_f16_kernel<<<dim3(3*DIMX/128, TOK/128), 256, GEMM_SMEM_BYTES>>>(
        nullptr, TOK, 3*DIMX, DIMX, 1);

    // 2. RMSNorm + RoPE (+ q-scale) fp32 -> fp16
    norm_rope_kernel<<<(2*BSZ*NH*SEQ)/8, 256>>>(qnw, knw);

    // 3. V transpose -> [bh][d][s] fp16
    transpose_v_kernel<<<dim3(SEQ/32, HD/32, BSZ*NH), dim3(32, 8)>>>();

    // 4. attention (fp16 MMA flash, Q-in-regs) -> g_y fp16
    attn_kernel<<<dim3(SEQ/128, BSZ*NH), 256, ATTN_SMEM_BYTES>>>();

    // 5. output projection (fp16 MMA, BK=64, 3-stage) -> fp32 out
    gemm_f16_kernel<<<dim3(DIMX/128, TOK/128), 256, GEMM_SMEM_BYTES>>>(
        out, TOK, DIMX, DIMX, 0);
}